// round 9
// baseline (speedup 1.0000x reference)
#include <cuda_runtime.h>

#define HW    2048
#define HW4   512
#define MASK  2047
#define BATCH 4
#define SY    32
#define WPB   2
#define NSTRIP 18          // 18 strips * 120 valid cols = 2160 >= 2048 (overlap rewrites identical values)
#define NBY   (HW / SY)    // 64

// folded constants
#define C0f     0.3623577545f      // cos(1.2)
#define S0f     0.9320390860f      // sin(1.2)
#define S02f    1.8640781720f      // 2*sin(1.2)
#define C02f    0.7247155090f      // 2*cos(1.2)
#define EPBf    0.19245009f        // EB  * sqrt(KB),  KB = (DT/TAU)/dx^2
#define EPDf    0.0038490018f      // EBD * sqrt(KB)
#define PCCf    (-0.0057735027f)   // M6EBD * KA / sqrt(KB),  KA = (DT/TAU)/(2dx)^2
#define KTf     0.1111111111f      // DT/dx^2
#define KAPf    1.8f
#define DTTAUf  0.3333333333f
#define APIXf   0.2864788976f      // alpha/pi
#define PIO2f   1.5707963268f

// stage1: P1/P2 pre-scaled by KA, E2 pre-scaled by KB (via eps' = eps*sqrt(KB))
__device__ __forceinline__ void stage1(float L, float R, float dn, float up,
                                       float& P1, float& P2, float& E2)
{
    float dx  = R - L;
    float dy  = up - dn;
    float dx2 = dx * dx;
    float dy2 = dy * dy;
    float r2  = dx2 + dy2;
    float t1  = fmaf(-3.0f, dy2, dx2);       // dx^2 - 3 dy^2
    float t2  = fmaf( 3.0f, dx2, -dy2);      // 3 dx^2 - dy^2
    float a3  = dx * t1;                     // Re(z^3)
    float b3  = dy * t2;                     // Im(z^3)
    float Az  = fmaf(a3, a3, -(b3 * b3));    // Re(z^6)
    float Bh  = a3 * b3;                     // Im(z^6)/2
    float r6  = r2 * r2 * r2;
    float ir6 = __fdividef(1.0f, fmaxf(r6, 1e-30f));
    float u   = fmaf(Az, C0f,  (Bh * S02f)) * ir6;   // cos(6(theta-theta0))
    float v   = fmaf(Bh, C02f, -(Az * S0f)) * ir6;   // sin(6(theta-theta0))
    float ep  = fmaf(EPDf, u, EPBf);        // eps * sqrt(KB)
    float pc  = ep * (PCCf * v);            // eps*eps_deriv*KA
    P1 =  pc * dx;
    P2 = -pc * dy;
    E2 = ep * ep;
}

__device__ __forceinline__ void stage1_quad(float lw, const float4& v, float rx,
                                            const float4& dn, const float4& up,
                                            float4& P1, float4& P2, float4& E2)
{
    stage1(lw,  v.y, dn.x, up.x, P1.x, P2.x, E2.x);
    stage1(v.x, v.z, dn.y, up.y, P1.y, P2.y, E2.y);
    stage1(v.y, v.w, dn.z, up.z, P1.z, P2.z, E2.z);
    stage1(v.z, rx,  dn.w, up.w, P1.w, P2.w, E2.w);
}

// atan for g in (0, 10]; 3-term odd minimax on [0,1]
__device__ __forceinline__ float atan_pos(float g)
{
    float inv = __fdividef(1.0f, g);
    float w   = fminf(g, inv);
    float w2  = w * w;
    float p   = fmaf(w2, 0.0793331f, -0.2886680f);
    p = fmaf(w2, p, 0.9953545f);
    p = p * w;
    return (g > 1.0f) ? (PIO2f - p) : p;
}

// stage2 for one column
__device__ __forceinline__ void stage2(float pl, float pc_, float pr, float pu, float pd,
                                       float tl, float tc, float tr, float tu, float td,
                                       float P1n, float P1m, float P2l, float P2r, float E2,
                                       float& op, float& ot)
{
    float lapp = (pu + pd) + (pl + pr);
    lapp = fmaf(pc_, -4.0f, lapp);
    float lapt = (tu + td) + (tl + tr);
    lapt = fmaf(tc, -4.0f, lapt);
    float term = (P1n - P1m) + (P2r - P2l);
    float at   = atan_pos(fmaf(tc, -10.0f, 10.0f));
    float marg = fmaf(APIXf, at, pc_ - 0.5f);
    float q    = fmaf(-pc_, pc_, pc_);
    float dphi = fmaf(E2, lapp, term);
    dphi = fmaf(q * marg, DTTAUf, dphi);
    op = pc_ + dphi;
    ot = fmaf(KAPf, dphi, fmaf(KTf, lapt, tc));
}

template<bool WRAP>
__device__ __forceinline__ void sweep_body(const float* __restrict__ phi,
                                           const float* __restrict__ tempr,
                                           float* __restrict__ out,
                                           int y0)
{
    const unsigned FULL = 0xffffffffu;
    const int lane  = threadIdx.x & 31;
    const int wid   = threadIdx.x >> 5;
    const int strip = blockIdx.x * WPB + wid;       // 0..17
    const int b     = blockIdx.z;
    const int lm    = lane - 1;
    const int lp    = lane + 1;

    // lane L owns cols strip*120 - 4 + 4L .. +3 ; lanes 1..30 produce output
    const int xb = (strip * 120 - 4 + 4 * lane) & MASK;
    const size_t base = (size_t)b * HW * HW;
    const float4* __restrict__ pb = (const float4*)(phi   + base) + (xb >> 2);
    const float4* __restrict__ tb = (const float4*)(tempr + base) + (xb >> 2);
    float4* __restrict__ po = (float4*)(out + base) + (xb >> 2);
    float4* __restrict__ to = (float4*)(out + (size_t)BATCH * HW * HW + base) + (xb >> 2);

#define PROW(r) pb[((r) & MASK) * HW4]
#define TROW(r) tb[((r) & MASK) * HW4]

    // prologue (wrap-safe via mask; one-time). pm2 is transient.
    float4 pm2 = PROW(y0 - 2), pm1 = PROW(y0 - 1), p0 = PROW(y0);
    float4 pp1 = PROW(y0 + 1), pp2 = PROW(y0 + 2);
    float4 tm1 = TROW(y0 - 1), t0 = TROW(y0), tp1 = TROW(y0 + 1);

    float4 P1m, P1c, P2c, E2c;
    {   // stage1 at row y0-1 (only P1 used)
        float lw = __shfl_sync(FULL, pm1.w, lm);
        float rx = __shfl_sync(FULL, pm1.x, lp);
        float4 d1, d2;
        stage1_quad(lw, pm1, rx, pm2, p0, P1m, d1, d2);
    }
    float lw0, rx0;   // carried x-halo of the p0 row
    {   // stage1 at row y0
        lw0 = __shfl_sync(FULL, p0.w, lm);
        rx0 = __shfl_sync(FULL, p0.x, lp);
        stage1_quad(lw0, p0, rx0, pm1, pp1, P1c, P2c, E2c);
    }

    const bool wr = (lane >= 1) && (lane <= 30);

    const float4* pld = pb + (size_t)(y0 + 3) * HW4;
    const float4* tld = tb + (size_t)(y0 + 2) * HW4;
    float4* por = po + (size_t)y0 * HW4;
    float4* tor = to + (size_t)y0 * HW4;

    #pragma unroll 2
    for (int i = 0; i < SY; ++i) {
        float4 pnew, tnew;
        if (WRAP) {
            pnew = PROW(y0 + i + 3);
            tnew = TROW(y0 + i + 2);
        } else {
            pnew = *pld;  pld += HW4;
            tnew = *tld;  tld += HW4;
        }

        // stage1 at row y+1 (shuffles double as next iter's stage2 halo)
        float lwP = __shfl_sync(FULL, pp1.w, lm);
        float rxP = __shfl_sync(FULL, pp1.x, lp);
        float4 P1n, P2n, E2n;
        stage1_quad(lwP, pp1, rxP, p0, pp2, P1n, P2n, E2n);

        // x-halos for stage2 at row y
        float lwT = __shfl_sync(FULL, t0.w,  lm);
        float rxT = __shfl_sync(FULL, t0.x,  lp);
        float lwQ = __shfl_sync(FULL, P2c.w, lm);
        float rxQ = __shfl_sync(FULL, P2c.x, lp);

        float4 outp, outt;
        stage2(lw0,  p0.x, p0.y, pp1.x, pm1.x,
               lwT,  t0.x, t0.y, tp1.x, tm1.x,
               P1n.x, P1m.x, lwQ,  P2c.y, E2c.x, outp.x, outt.x);
        stage2(p0.x, p0.y, p0.z, pp1.y, pm1.y,
               t0.x, t0.y, t0.z, tp1.y, tm1.y,
               P1n.y, P1m.y, P2c.x, P2c.z, E2c.y, outp.y, outt.y);
        stage2(p0.y, p0.z, p0.w, pp1.z, pm1.z,
               t0.y, t0.z, t0.w, tp1.z, tm1.z,
               P1n.z, P1m.z, P2c.y, P2c.w, E2c.z, outp.z, outt.z);
        stage2(p0.z, p0.w, rx0,  pp1.w, pm1.w,
               t0.z, t0.w, rxT,  tp1.w, tm1.w,
               P1n.w, P1m.w, P2c.z, rxQ,  E2c.w, outp.w, outt.w);

        if (wr) {
            __stcs(por, outp);      // streaming: outputs never re-read
            __stcs(tor, outt);
        }
        por += HW4;
        tor += HW4;

        // ring shifts
        pm1 = p0;  p0 = pp1;  pp1 = pp2;  pp2 = pnew;
        tm1 = t0;  t0 = tp1;  tp1 = tnew;
        P1m = P1c; P1c = P1n; P2c = P2n; E2c = E2n;
        lw0 = lwP; rx0 = rxP;
    }
#undef PROW
#undef TROW
}

__global__ __launch_bounds__(WPB * 32, 10)
void dendrite_sweep7(const float* __restrict__ phi,
                     const float* __restrict__ tempr,
                     float* __restrict__ out)
{
    const int by = blockIdx.y;
    const int y0 = by * SY;
    if (by == 0 || by == NBY - 1) {
        sweep_body<true>(phi, tempr, out, y0);
    } else {
        sweep_body<false>(phi, tempr, out, y0);
    }
}

extern "C" void kernel_launch(void* const* d_in, const int* in_sizes, int n_in,
                              void* d_out, int out_size)
{
    const float* phi   = (const float*)d_in[0];
    const float* tempr = (const float*)d_in[1];
    float* out = (float*)d_out;

    dim3 block(WPB * 32);
    dim3 grid(NSTRIP / WPB, NBY, BATCH);   // (9, 64, 4) = 2304 CTAs
    dendrite_sweep7<<<grid, block>>>(phi, tempr, out);
}

// round 10
// speedup vs baseline: 1.2547x; 1.2547x over previous
#include <cuda_runtime.h>

#define HW    2048
#define HW2   1024
#define MASK  2047
#define BATCH 4
#define SY    64
#define WPB   4
#define NSTRIP 36          // 36*60 = 2160 >= 2048; overlap strips rewrite identical wrapped values
#define NBY   (HW / SY)    // 32

// folded constants
#define C0f     0.3623577545f      // cos(1.2)
#define S0f     0.9320390860f      // sin(1.2)
#define S02f    1.8640781720f      // 2*sin(1.2)
#define C02f    0.7247155090f      // 2*cos(1.2)
#define EPBf    0.19245009f        // EB  * sqrt(KB),  KB = (DT/TAU)/dx^2
#define EPDf    0.0038490018f      // EBD * sqrt(KB)
#define PCCf    (-0.0057735027f)   // M6EBD * KA / sqrt(KB),  KA = (DT/TAU)/(2dx)^2
#define KTf     0.1111111111f      // DT/dx^2
#define KAPf    1.8f
#define DTTAUf  0.3333333333f
#define APIXf   0.2864788976f      // alpha/pi
#define PIO2f   1.5707963268f

// stage1: P1/P2 pre-scaled by KA, E2 pre-scaled by KB (via eps' = eps*sqrt(KB))
__device__ __forceinline__ void stage1(float L, float R, float dn, float up,
                                       float& P1, float& P2, float& E2)
{
    float dx  = R - L;
    float dy  = up - dn;
    float dx2 = dx * dx;
    float dy2 = dy * dy;
    float r2  = dx2 + dy2;
    float t1  = fmaf(-3.0f, dy2, dx2);       // dx^2 - 3 dy^2
    float t2  = fmaf( 3.0f, dx2, -dy2);      // 3 dx^2 - dy^2
    float a3  = dx * t1;                     // Re(z^3)
    float b3  = dy * t2;                     // Im(z^3)
    float Az  = fmaf(a3, a3, -(b3 * b3));    // Re(z^6)
    float Bh  = a3 * b3;                     // Im(z^6)/2
    float r6  = r2 * r2 * r2;
    float ir6 = __fdividef(1.0f, fmaxf(r6, 1e-30f));
    float u   = fmaf(Az, C0f,  (Bh * S02f)) * ir6;   // cos(6(theta-theta0))
    float v   = fmaf(Bh, C02f, -(Az * S0f)) * ir6;   // sin(6(theta-theta0))
    float ep  = fmaf(EPDf, u, EPBf);        // eps * sqrt(KB)
    float pc  = ep * (PCCf * v);            // eps*eps_deriv*KA
    P1 =  pc * dx;
    P2 = -pc * dy;
    E2 = ep * ep;
}

// atan for g in (0, 10]; 3-term odd minimax on [0,1] (err ~6e-4 rad)
__device__ __forceinline__ float atan_pos(float g)
{
    float inv = __fdividef(1.0f, g);
    float w   = fminf(g, inv);
    float w2  = w * w;
    float p   = fmaf(w2, 0.0793331f, -0.2886680f);
    p = fmaf(w2, p, 0.9953545f);
    p = p * w;
    return (g > 1.0f) ? (PIO2f - p) : p;
}

template<bool WRAP>
__device__ __forceinline__ void sweep_body(const float* __restrict__ phi,
                                           const float* __restrict__ tempr,
                                           float* __restrict__ out,
                                           int y0)
{
    const unsigned FULL = 0xffffffffu;
    const int lane  = threadIdx.x & 31;
    const int wid   = threadIdx.x >> 5;
    const int strip = blockIdx.x * WPB + wid;       // 0..35
    const int b     = blockIdx.z;
    const int lm    = lane - 1;
    const int lp    = lane + 1;

    const int xc = (strip * 60 - 2 + 2 * lane) & MASK;
    const size_t base = (size_t)b * HW * HW;
    const float2* __restrict__ pb = (const float2*)(phi   + base) + (xc >> 1);
    const float2* __restrict__ tb = (const float2*)(tempr + base) + (xc >> 1);
    float2* __restrict__ po = (float2*)(out + base) + (xc >> 1);
    float2* __restrict__ to = (float2*)(out + (size_t)BATCH * HW * HW + base) + (xc >> 1);

#define PROW(r) pb[((r) & MASK) * HW2]
#define TROW(r) tb[((r) & MASK) * HW2]

    // prologue (wrap-safe via mask; one-time). pm2 is transient.
    float2 pm2 = PROW(y0 - 2), pm1 = PROW(y0 - 1), p0 = PROW(y0);
    float2 pp1 = PROW(y0 + 1), pp2 = PROW(y0 + 2);
    float2 tm1 = TROW(y0 - 1), t0 = TROW(y0), tp1 = TROW(y0 + 1);

    float2 P1m, P1c, P2c, E2c;
    {
        float Lc = __shfl_sync(FULL, pm1.y, lm);
        float Rc = __shfl_sync(FULL, pm1.x, lp);
        float d0, d1;
        stage1(Lc,    pm1.y, pm2.x, p0.x, P1m.x, d0, d1);
        stage1(pm1.x, Rc,    pm2.y, p0.y, P1m.y, d0, d1);
    }
    {
        float Lc = __shfl_sync(FULL, p0.y, lm);
        float Rc = __shfl_sync(FULL, p0.x, lp);
        stage1(Lc,   p0.y, pm1.x, pp1.x, P1c.x, P2c.x, E2c.x);
        stage1(p0.x, Rc,   pm1.y, pp1.y, P1c.y, P2c.y, E2c.y);
    }

    const bool wr = (lane >= 1) && (lane <= 30);

    // marching pointers (interior path: no mask, no per-iter index math)
    const float2* pld = pb + (size_t)(y0 + 3) * HW2;
    const float2* tld = tb + (size_t)(y0 + 2) * HW2;
    float2* por = po + (size_t)y0 * HW2;
    float2* tor = to + (size_t)y0 * HW2;

    #pragma unroll 4
    for (int i = 0; i < SY; ++i) {
        float2 pnew, tnew;
        if (WRAP) {
            pnew = PROW(y0 + i + 3);
            tnew = TROW(y0 + i + 2);
        } else {
            pnew = *pld;  pld += HW2;
            tnew = *tld;  tld += HW2;
        }

        float2 P1n, P2n, E2n;
        {
            float Lc = __shfl_sync(FULL, pp1.y, lm);
            float Rc = __shfl_sync(FULL, pp1.x, lp);
            stage1(Lc,    pp1.y, p0.x, pp2.x, P1n.x, P2n.x, E2n.x);
            stage1(pp1.x, Rc,    p0.y, pp2.y, P1n.y, P2n.y, E2n.y);
        }

        float Lp  = __shfl_sync(FULL, p0.y,  lm);
        float Rp  = __shfl_sync(FULL, p0.x,  lp);
        float Lt  = __shfl_sync(FULL, t0.y,  lm);
        float Rt  = __shfl_sync(FULL, t0.x,  lp);
        float LP2 = __shfl_sync(FULL, P2c.y, lm);
        float RP2 = __shfl_sync(FULL, P2c.x, lp);

        float2 outp, outt;
        {   // column xc
            float lapp = (pp1.x + pm1.x) + (Lp + p0.y);
            lapp = fmaf(p0.x, -4.0f, lapp);
            float lapt = (tp1.x + tm1.x) + (Lt + t0.y);
            lapt = fmaf(t0.x, -4.0f, lapt);
            float term = (P1n.x - P1m.x) + (P2c.y - LP2);   // KA pre-folded
            float at   = atan_pos(fmaf(t0.x, -10.0f, 10.0f));
            float marg = fmaf(APIXf, at, p0.x - 0.5f);
            float q    = fmaf(-p0.x, p0.x, p0.x);
            float dphi = fmaf(E2c.x, lapp, term);           // KB pre-folded
            dphi = fmaf(q * marg, DTTAUf, dphi);
            outp.x = p0.x + dphi;
            outt.x = fmaf(KAPf, dphi, fmaf(KTf, lapt, t0.x));
        }
        {   // column xc+1
            float lapp = (pp1.y + pm1.y) + (p0.x + Rp);
            lapp = fmaf(p0.y, -4.0f, lapp);
            float lapt = (tp1.y + tm1.y) + (t0.x + Rt);
            lapt = fmaf(t0.y, -4.0f, lapt);
            float term = (P1n.y - P1m.y) + (RP2 - P2c.x);
            float at   = atan_pos(fmaf(t0.y, -10.0f, 10.0f));
            float marg = fmaf(APIXf, at, p0.y - 0.5f);
            float q    = fmaf(-p0.y, p0.y, p0.y);
            float dphi = fmaf(E2c.y, lapp, term);
            dphi = fmaf(q * marg, DTTAUf, dphi);
            outp.y = p0.y + dphi;
            outt.y = fmaf(KAPf, dphi, fmaf(KTf, lapt, t0.y));
        }

        if (wr) {
            __stcs(por, outp);      // streaming: outputs never re-read
            __stcs(tor, outt);
        }
        por += HW2;
        tor += HW2;

        pm1 = p0;  p0 = pp1;  pp1 = pp2;  pp2 = pnew;
        tm1 = t0;  t0 = tp1;  tp1 = tnew;
        P1m = P1c; P1c = P1n; P2c = P2n; E2c = E2n;
    }
#undef PROW
#undef TROW
}

__global__ __launch_bounds__(WPB * 32, 8)
void dendrite_sweep8(const float* __restrict__ phi,
                     const float* __restrict__ tempr,
                     float* __restrict__ out)
{
    const int by = blockIdx.y;
    const int y0 = by * SY;
    if (by == 0 || by == NBY - 1) {
        sweep_body<true>(phi, tempr, out, y0);
    } else {
        sweep_body<false>(phi, tempr, out, y0);
    }
}

extern "C" void kernel_launch(void* const* d_in, const int* in_sizes, int n_in,
                              void* d_out, int out_size)
{
    const float* phi   = (const float*)d_in[0];
    const float* tempr = (const float*)d_in[1];
    float* out = (float*)d_out;

    dim3 block(WPB * 32);
    dim3 grid(NSTRIP / WPB, NBY, BATCH);   // (9, 32, 4) = 1152 CTAs -> single wave @ 8/SM
    dendrite_sweep8<<<grid, block>>>(phi, tempr, out);
}